// round 1
// baseline (speedup 1.0000x reference)
#include <cuda_runtime.h>
#include <cuda_bf16.h>

#define NUM_BINS 32
#define FULL_MASK 0xFFFFFFFFu

// One warp per row. Lane k owns bin k (W) and vertex k (V).
__global__ __launch_bounds__(256, 8)
void pwq_coupling_kernel(const float* __restrict__ x_b,
                         const float* __restrict__ W,
                         const float* __restrict__ V,
                         float* __restrict__ out,   // [0:n)=z, [n:2n)=log_det
                         int n)
{
    const int lane   = threadIdx.x & 31;
    const int warpId = threadIdx.x >> 5;
    const int row    = blockIdx.x * (blockDim.x >> 5) + warpId;
    if (row >= n) return;

    // Coalesced row loads: issue all global loads up front for MLP.
    const float w   = W[(size_t)row * NUM_BINS + lane];          // W[row, lane]
    const float vlo = V[(size_t)row * (NUM_BINS + 1) + lane];    // V[row, lane]
    float vlast = 0.0f;
    if (lane == 31) vlast = V[(size_t)row * (NUM_BINS + 1) + NUM_BINS]; // V[row,32]
    const float x = x_b[row];

    // v_next[k] = V[row, k+1]
    float v_next = __shfl_down_sync(FULL_MASK, vlo, 1);
    if (lane == 31) v_next = vlast;

    // Trapezoid area of this bin
    const float area = 0.5f * (vlo + v_next) * w;

    // Inclusive warp scans (cumsum) of w and area
    float cw = w;
    float ca = area;
    #pragma unroll
    for (int d = 1; d < 32; d <<= 1) {
        float tw = __shfl_up_sync(FULL_MASK, cw, d);
        float ta = __shfl_up_sync(FULL_MASK, ca, d);
        if (lane >= d) { cw += tw; ca += ta; }
    }
    const float edge     = cw - w;    // exclusive prefix = left edge of bin k
    const float area_pre = ca - area; // CDF at left edge of bin k

    // Bin search: reference counts edges (incl. edge0=0, edge32 forced to 1).
    // val in [0, 0.9999] => edge0 always counted, edge32 never. So:
    const float val = fminf(fmaxf(x, 0.0f), 0.9999f);
    const unsigned ballot = __ballot_sync(FULL_MASK, val >= edge);
    int bin = __popc(ballot) - 1;            // in [0, 31] (lane0 edge=0 always true)

    // Broadcast the selected bin's quantities to lane 0
    const float w_b    = __shfl_sync(FULL_MASK, w,        bin);
    const float v_b    = __shfl_sync(FULL_MASK, vlo,      bin);
    const float v_b1   = __shfl_sync(FULL_MASK, v_next,   bin);
    const float edge_b = __shfl_sync(FULL_MASK, edge,     bin);
    const float apre_b = __shfl_sync(FULL_MASK, area_pre, bin);

    if (lane == 0) {
        const float alpha = (val - edge_b) / (w_b + 1e-8f);
        const float dv    = v_b1 - v_b;
        const float z     = apre_b + alpha * v_b * w_b
                          + 0.5f * alpha * alpha * dv * w_b;
        const float pdf   = v_b + alpha * dv;
        out[row]     = z;
        out[n + row] = logf(pdf + 1e-8f);
    }
}

extern "C" void kernel_launch(void* const* d_in, const int* in_sizes, int n_in,
                              void* d_out, int out_size)
{
    const float* x_b = (const float*)d_in[0];
    const float* W   = (const float*)d_in[1];
    const float* V   = (const float*)d_in[2];
    float* out = (float*)d_out;

    const int n = in_sizes[0];             // N rows (x_b has N elements)
    const int warpsPerBlock = 8;           // 256 threads
    const int blocks = (n + warpsPerBlock - 1) / warpsPerBlock;
    pwq_coupling_kernel<<<blocks, warpsPerBlock * 32>>>(x_b, W, V, out, n);
}

// round 2
// speedup vs baseline: 3.0370x; 3.0370x over previous
#include <cuda_runtime.h>
#include <cuda_bf16.h>

#define FULL_MASK 0xFFFFFFFFu

// 8 lanes per row, 4 rows per warp. Lane t (0..7) owns bins 4t..4t+3.
__global__ __launch_bounds__(256, 8)
void pwq_coupling_kernel(const float* __restrict__ x_b,
                         const float* __restrict__ W,
                         const float* __restrict__ V,
                         float* __restrict__ out,   // [0:n)=z, [n:2n)=log_det
                         int n)
{
    const int lane = threadIdx.x & 31;
    const int t    = lane & 7;                 // sublane within 8-lane segment
    const int warpGlobal = (blockIdx.x * blockDim.x + threadIdx.x) >> 5;
    const int row = warpGlobal * 4 + (lane >> 3);
    if (row >= n) return;                      // n % 4 == 0: whole warp exits together

    // ---- loads (issued up front for MLP) ----
    const float4 w4 = *(const float4*)(W + (size_t)row * 32 + t * 4);  // 16B aligned
    const float* Vrow = V + (size_t)row * 33 + t * 4;                  // 132B stride: scalar
    float v0 = Vrow[0];
    float v1 = Vrow[1];
    float v2 = Vrow[2];
    float v3 = Vrow[3];
    const float x = x_b[row];                  // 8 lanes same addr -> broadcast

    // 5th vertex: neighbor's v0 within the segment; lane t=7 loads V[row,32]
    float v4 = __shfl_down_sync(FULL_MASK, v0, 1, 8);
    if (t == 7) v4 = Vrow[4];

    // ---- local trapezoid areas ----
    const float a0 = 0.5f * (v0 + v1) * w4.x;
    const float a1 = 0.5f * (v1 + v2) * w4.y;
    const float a2 = 0.5f * (v2 + v3) * w4.z;
    const float a3 = 0.5f * (v3 + v4) * w4.w;

    // ---- local inclusive prefixes (4 elems) ----
    const float lw1 = w4.x + w4.y;
    const float lw2 = lw1 + w4.z;
    const float lw3 = lw2 + w4.w;
    const float la1 = a0 + a1;
    const float la2 = la1 + a2;
    const float la3 = la2 + a3;

    // ---- segmented 8-lane scan of segment totals ----
    float cw = lw3, ca = la3;
    #pragma unroll
    for (int d = 1; d < 8; d <<= 1) {
        const float tw = __shfl_up_sync(FULL_MASK, cw, d, 8);
        const float ta = __shfl_up_sync(FULL_MASK, ca, d, 8);
        if (t >= d) { cw += tw; ca += ta; }
    }
    const float bw = cw - lw3;                 // exclusive prefix: left edge of bin 4t
    const float ba = ca - la3;                 // CDF at left edge of bin 4t

    // inclusive W-cumsum at this lane's 4 bins = edges[4t+1 .. 4t+4]
    const float cw0 = bw + w4.x;
    const float cw1 = bw + lw1;
    const float cw2 = bw + lw2;
    const float cw3 = bw + lw3;

    // ---- bin search: count interior edges <= val across the row ----
    const float val = fminf(fmaxf(x, 0.0f), 0.9999f);
    int cnt = (int)(val >= cw0) + (int)(val >= cw1)
            + (int)(val >= cw2) + (int)(val >= cw3);
    #pragma unroll
    for (int d = 1; d < 8; d <<= 1)
        cnt += __shfl_xor_sync(FULL_MASK, cnt, d, 8);
    const int bin = min(cnt, 31);              // matches reference clip semantics
    const int o = bin >> 2;                    // owner sublane
    const int j = bin & 3;                     // local index within owner

    // ---- each lane selects its local j-th candidate (owner's is the real one) ----
    const bool j1 = (j & 1), j2 = (j & 2);
    const float e_sel  = j2 ? (j1 ? cw2 : cw1) : (j1 ? cw0 : bw);   // left edge of bin
    const float p1 = ba + a0, p2 = ba + la1, p3 = ba + la2;
    const float p_sel  = j2 ? (j1 ? p3 : p2) : (j1 ? p1 : ba);      // area_pre
    const float w_sel  = j2 ? (j1 ? w4.w : w4.z) : (j1 ? w4.y : w4.x);
    const float vb_sel = j2 ? (j1 ? v3 : v2) : (j1 ? v1 : v0);
    const float v1_sel = j2 ? (j1 ? v4 : v3) : (j1 ? v2 : v1);

    // ---- broadcast from the owning sublane ----
    const float w_b    = __shfl_sync(FULL_MASK, w_sel,  o, 8);
    const float v_b    = __shfl_sync(FULL_MASK, vb_sel, o, 8);
    const float v_b1   = __shfl_sync(FULL_MASK, v1_sel, o, 8);
    const float edge_b = __shfl_sync(FULL_MASK, e_sel,  o, 8);
    const float apre_b = __shfl_sync(FULL_MASK, p_sel,  o, 8);

    if (t == 0) {
        const float alpha = __fdividef(val - edge_b, w_b + 1e-8f);
        const float dv    = v_b1 - v_b;
        const float z     = apre_b + alpha * w_b * (v_b + 0.5f * alpha * dv);
        out[row]     = z;
        out[n + row] = __logf(v_b + alpha * dv + 1e-8f);
    }
}

extern "C" void kernel_launch(void* const* d_in, const int* in_sizes, int n_in,
                              void* d_out, int out_size)
{
    const float* x_b = (const float*)d_in[0];
    const float* W   = (const float*)d_in[1];
    const float* V   = (const float*)d_in[2];
    float* out = (float*)d_out;

    const int n = in_sizes[0];                     // N rows
    const int rowsPerBlock = 32;                   // 256 threads = 8 warps * 4 rows
    const int blocks = (n + rowsPerBlock - 1) / rowsPerBlock;
    pwq_coupling_kernel<<<blocks, 256>>>(x_b, W, V, out, n);
}